// round 12
// baseline (speedup 1.0000x reference)
#include <cuda_runtime.h>
#include <cuda_bf16.h>
#include <mma.h>
#include <math.h>

// ---------------------------------------------------------------------------
// Problem dims (fixed)
// ---------------------------------------------------------------------------
#define S_  2048
#define B_  2
#define E_  1024
#define H_  16
#define D_  64
#define M_  (S_ * B_)
#define BHn (B_ * H_)
#define ST_ ((size_t)S_ * S_)

// ---------------------------------------------------------------------------
// Device scratch (static). ~700 MB total (fp32 scores tensor eliminated).
// ---------------------------------------------------------------------------
__device__ __align__(128) __nv_bfloat16 g_Qh[(size_t)BHn * S_ * D_];
__device__ __align__(128) __nv_bfloat16 g_Ql[(size_t)BHn * S_ * D_];
__device__ __align__(128) __nv_bfloat16 g_Kh[(size_t)BHn * S_ * D_];
__device__ __align__(128) __nv_bfloat16 g_Kl[(size_t)BHn * S_ * D_];
__device__ __align__(128) __nv_bfloat16 g_Vh[(size_t)BHn * S_ * D_];
__device__ __align__(128) __nv_bfloat16 g_Vl[(size_t)BHn * S_ * D_];
__device__ __align__(128) __nv_bfloat16 g_Ph[(size_t)BHn * ST_];
__device__ __align__(128) __nv_bfloat16 g_Pl[(size_t)BHn * ST_];
__device__ float g_ctx[(size_t)M_ * E_];

__device__ __align__(128) __nv_bfloat16 g_xh[(size_t)M_ * E_];
__device__ __align__(128) __nv_bfloat16 g_xl[(size_t)M_ * E_];
__device__ __align__(128) __nv_bfloat16 g_Wh[(size_t)4 * E_ * E_];
__device__ __align__(128) __nv_bfloat16 g_Wl[(size_t)4 * E_ * E_];
__device__ __align__(128) __nv_bfloat16 g_ch[(size_t)M_ * E_];
__device__ __align__(128) __nv_bfloat16 g_cl[(size_t)M_ * E_];

using namespace nvcuda;

// ---------------------------------------------------------------------------
// Split fp32 -> bf16 hi + bf16 lo (residual). Vectorized by 4.
// ---------------------------------------------------------------------------
__global__ void __launch_bounds__(256)
conv_split(const float* __restrict__ src, __nv_bfloat16* __restrict__ hi,
           __nv_bfloat16* __restrict__ lo, int n4)
{
    int idx = blockIdx.x * 256 + threadIdx.x;
    if (idx >= n4) return;
    float4 vin = reinterpret_cast<const float4*>(src)[idx];
    float vals[4];
    vals[0] = vin.x; vals[1] = vin.y; vals[2] = vin.z; vals[3] = vin.w;
    __nv_bfloat16 hiv[4];
    __nv_bfloat16 lov[4];
    #pragma unroll
    for (int j = 0; j < 4; ++j) {
        hiv[j] = __float2bfloat16_rn(vals[j]);
        lov[j] = __float2bfloat16_rn(vals[j] - __bfloat162float(hiv[j]));
    }
    __nv_bfloat162* hp = reinterpret_cast<__nv_bfloat162*>(hi);
    __nv_bfloat162* lp = reinterpret_cast<__nv_bfloat162*>(lo);
    hp[2 * idx + 0] = __nv_bfloat162(hiv[0], hiv[1]);
    hp[2 * idx + 1] = __nv_bfloat162(hiv[2], hiv[3]);
    lp[2 * idx + 0] = __nv_bfloat162(lov[0], lov[1]);
    lp[2 * idx + 1] = __nv_bfloat162(lov[2], lov[3]);
}

// ---------------------------------------------------------------------------
// WMMA projection GEMM (unchanged from R10 pass). BM=BN=128, BK=32,
// 2-stage smem + register prefetch, 3-product hi/lo split.
// mode 0/1/2: write bf16 hi/lo Q/K/V [b][h][s][d]; mode 3: fp32 outp[m][n].
// ---------------------------------------------------------------------------
#define SKP        40
#define TILE_E     (128 * SKP)
#define STAGE_E    (4 * TILE_E)
#define GEMM_SMEM  (2 * STAGE_E * 2)

__global__ void __launch_bounds__(256)
wmma_gemm(const __nv_bfloat16* __restrict__ Ahp, const __nv_bfloat16* __restrict__ Alp,
          const __nv_bfloat16* __restrict__ Whp, const __nv_bfloat16* __restrict__ Wlp,
          const float* __restrict__ bias, float* __restrict__ outp, int mode)
{
    extern __shared__ __align__(16) unsigned char smraw[];
    __nv_bfloat16* smb = reinterpret_cast<__nv_bfloat16*>(smraw);

    const int tid    = threadIdx.x;
    const int lane   = tid & 31;
    const int warpid = tid >> 5;
    const int warpM  = (warpid >> 2) << 6;
    const int warpN  = (warpid & 3) << 5;
    const int blockM = blockIdx.y << 7;
    const int blockN = blockIdx.x << 7;

    const __nv_bfloat16* gT[4];
    gT[0] = Ahp + (size_t)blockM * 1024;
    gT[1] = Alp + (size_t)blockM * 1024;
    gT[2] = Whp + (size_t)blockN * 1024;
    gT[3] = Wlp + (size_t)blockN * 1024;

    const int srow  = tid >> 1;
    const int shalf = tid & 1;

    wmma::fragment<wmma::accumulator, 16, 16, 16, float> accf[4][2];
    #pragma unroll
    for (int mi = 0; mi < 4; ++mi)
        #pragma unroll
        for (int nj = 0; nj < 2; ++nj)
            wmma::fill_fragment(accf[mi][nj], 0.0f);

    float4 pre[8];
    #pragma unroll
    for (int t = 0; t < 4; ++t)
        #pragma unroll
        for (int c = 0; c < 2; ++c)
            pre[t * 2 + c] = *reinterpret_cast<const float4*>(
                gT[t] + (size_t)srow * 1024 + (size_t)(shalf * 2 + c) * 8);
    #pragma unroll
    for (int t = 0; t < 4; ++t)
        #pragma unroll
        for (int c = 0; c < 2; ++c)
            *reinterpret_cast<float4*>(
                smb + t * TILE_E + srow * SKP + (shalf * 2 + c) * 8) = pre[t * 2 + c];

    for (int step = 0; step < 32; ++step) {
        if (step < 31) {
            size_t k0 = (size_t)(step + 1) * 32;
            #pragma unroll
            for (int t = 0; t < 4; ++t)
                #pragma unroll
                for (int c = 0; c < 2; ++c)
                    pre[t * 2 + c] = *reinterpret_cast<const float4*>(
                        gT[t] + (size_t)srow * 1024 + k0 + (size_t)(shalf * 2 + c) * 8);
        }
        __syncthreads();

        const __nv_bfloat16* stg = smb + (step & 1) * STAGE_E;
        #pragma unroll
        for (int kk = 0; kk < 2; ++kk) {
            wmma::fragment<wmma::matrix_a, 16, 16, 16, __nv_bfloat16, wmma::row_major> fAh[4];
            wmma::fragment<wmma::matrix_a, 16, 16, 16, __nv_bfloat16, wmma::row_major> fAl[4];
            wmma::fragment<wmma::matrix_b, 16, 16, 16, __nv_bfloat16, wmma::col_major> fBh[2];
            wmma::fragment<wmma::matrix_b, 16, 16, 16, __nv_bfloat16, wmma::col_major> fBl[2];
            #pragma unroll
            for (int mi = 0; mi < 4; ++mi) {
                wmma::load_matrix_sync(fAh[mi],
                    stg + 0 * TILE_E + (warpM + mi * 16) * SKP + kk * 16, SKP);
                wmma::load_matrix_sync(fAl[mi],
                    stg + 1 * TILE_E + (warpM + mi * 16) * SKP + kk * 16, SKP);
            }
            #pragma unroll
            for (int nj = 0; nj < 2; ++nj) {
                wmma::load_matrix_sync(fBh[nj],
                    stg + 2 * TILE_E + (warpN + nj * 16) * SKP + kk * 16, SKP);
                wmma::load_matrix_sync(fBl[nj],
                    stg + 3 * TILE_E + (warpN + nj * 16) * SKP + kk * 16, SKP);
            }
            #pragma unroll
            for (int mi = 0; mi < 4; ++mi) {
                #pragma unroll
                for (int nj = 0; nj < 2; ++nj) {
                    wmma::mma_sync(accf[mi][nj], fAh[mi], fBh[nj], accf[mi][nj]);
                    wmma::mma_sync(accf[mi][nj], fAh[mi], fBl[nj], accf[mi][nj]);
                    wmma::mma_sync(accf[mi][nj], fAl[mi], fBh[nj], accf[mi][nj]);
                }
            }
        }
        if (step < 31) {
            __nv_bfloat16* nstg = smb + ((step + 1) & 1) * STAGE_E;
            #pragma unroll
            for (int t = 0; t < 4; ++t)
                #pragma unroll
                for (int c = 0; c < 2; ++c)
                    *reinterpret_cast<float4*>(
                        nstg + t * TILE_E + srow * SKP + (shalf * 2 + c) * 8) = pre[t * 2 + c];
        }
    }

    __syncthreads();
    float* stgf = reinterpret_cast<float*>(smraw) + warpid * 576;

    __nv_bfloat16* dsth = (mode == 0) ? g_Qh : (mode == 1) ? g_Kh : g_Vh;
    __nv_bfloat16* dstl = (mode == 0) ? g_Ql : (mode == 1) ? g_Kl : g_Vl;

    const int erow = lane >> 1;
    const int ecol = (lane & 1) * 16;

    #pragma unroll
    for (int mi = 0; mi < 4; ++mi) {
        wmma::store_matrix_sync(stgf + 0,  accf[mi][0], 36, wmma::mem_row_major);
        wmma::store_matrix_sync(stgf + 16, accf[mi][1], 36, wmma::mem_row_major);
        __syncwarp();

        int mRow = blockM + warpM + mi * 16 + erow;
        int col0 = blockN + warpN + ecol;

        float vv[16];
        #pragma unroll
        for (int c = 0; c < 4; ++c) {
            float4 t4 = *reinterpret_cast<const float4*>(stgf + erow * 36 + ecol + c * 4);
            float4 b4 = *reinterpret_cast<const float4*>(bias + col0 + c * 4);
            vv[c * 4 + 0] = t4.x + b4.x;
            vv[c * 4 + 1] = t4.y + b4.y;
            vv[c * 4 + 2] = t4.z + b4.z;
            vv[c * 4 + 3] = t4.w + b4.w;
        }

        if (mode <= 2) {
            int sE = mRow >> 1;
            int bE = mRow & 1;
            int hE = col0 >> 6;
            int dE = col0 & 63;
            unsigned int pwh[8];
            unsigned int pwl[8];
            #pragma unroll
            for (int j = 0; j < 8; ++j) {
                __nv_bfloat16 h0 = __float2bfloat16_rn(vv[2 * j]);
                __nv_bfloat16 h1 = __float2bfloat16_rn(vv[2 * j + 1]);
                __nv_bfloat16 l0 = __float2bfloat16_rn(vv[2 * j] - __bfloat162float(h0));
                __nv_bfloat16 l1 = __float2bfloat16_rn(vv[2 * j + 1] - __bfloat162float(h1));
                pwh[j] = (unsigned int)__bfloat16_as_ushort(h0)
                       | ((unsigned int)__bfloat16_as_ushort(h1) << 16);
                pwl[j] = (unsigned int)__bfloat16_as_ushort(l0)
                       | ((unsigned int)__bfloat16_as_ushort(l1) << 16);
            }
            size_t base = ((((size_t)bE * H_ + hE) * S_ + sE) << 6) + dE;
            uint4* ph = reinterpret_cast<uint4*>(dsth + base);
            uint4* pl = reinterpret_cast<uint4*>(dstl + base);
            ph[0] = make_uint4(pwh[0], pwh[1], pwh[2], pwh[3]);
            ph[1] = make_uint4(pwh[4], pwh[5], pwh[6], pwh[7]);
            pl[0] = make_uint4(pwl[0], pwl[1], pwl[2], pwl[3]);
            pl[1] = make_uint4(pwl[4], pwl[5], pwl[6], pwl[7]);
        } else {
            float* pd = outp + (size_t)mRow * 1024 + col0;
            #pragma unroll
            for (int c = 0; c < 4; ++c)
                *reinterpret_cast<float4*>(pd + c * 4)
                    = make_float4(vv[c*4+0], vv[c*4+1], vv[c*4+2], vv[c*4+3]);
        }
        __syncwarp();
    }
}

// ---------------------------------------------------------------------------
// FUSED scores + head-softmax. Block = (t32, s64, b) covering ALL 16 heads.
// Per head: stream Q (64x64) / K (32x64) hi/lo tiles into smem, 3-product
// WMMA into fp32 score plane (smem, stride 36). Then softmax over h in-block,
// emit post-softmax bf16 hi/lo directly to g_Ph/g_Pl. No fp32 score tensor.
// Smem: 16*64*36*4 = 147456 (scores) + Q 2*64*72*2 = 18432 + K 2*32*72*2
//     = 9216 -> 175104 B.
// ---------------------------------------------------------------------------
#define SS_S    64
#define SS_T    32
#define SPAD    36
#define SPLANE  (SS_S * SPAD)                 // 2304 floats per head plane
#define SC_OFF  0
#define QH_OFF  (16 * SPLANE * 4)             // 147456
#define QL_OFF  (QH_OFF + SS_S * 72 * 2)      // +9216
#define KH_OFF  (QL_OFF + SS_S * 72 * 2)      // +9216
#define KL_OFF  (KH_OFF + SS_T * 72 * 2)      // +4608
#define SS_SMEM (KL_OFF + SS_T * 72 * 2)      // 175104

__device__ __forceinline__ float exp_poly(float x)
{
    float t = x * 1.4426950408889634f;
    t = fmaxf(t, -80.0f);
    float fi = floorf(t);
    float f = t - fi;
    float p = 0.0001540353f;
    p = p * f + 0.0013333558f;
    p = p * f + 0.0096181291f;
    p = p * f + 0.0555041087f;
    p = p * f + 0.2402265069f;
    p = p * f + 0.6931471806f;
    p = p * f + 1.0f;
    int ei = (int)fi + 127;
    float sc = __uint_as_float(((unsigned int)ei) << 23);
    return p * sc;
}

__global__ void __launch_bounds__(256)
scores_softmax()
{
    extern __shared__ __align__(16) unsigned char smraw[];
    float*         sSc = reinterpret_cast<float*>(smraw + SC_OFF);
    __nv_bfloat16* sQh = reinterpret_cast<__nv_bfloat16*>(smraw + QH_OFF);
    __nv_bfloat16* sQl = reinterpret_cast<__nv_bfloat16*>(smraw + QL_OFF);
    __nv_bfloat16* sKh = reinterpret_cast<__nv_bfloat16*>(smraw + KH_OFF);
    __nv_bfloat16* sKl = reinterpret_cast<__nv_bfloat16*>(smraw + KL_OFF);

    const int tid    = threadIdx.x;
    const int warpid = tid >> 5;
    const int wmi    = warpid & 3;             // 0..3 -> s sub-tile
    const int wnj    = warpid >> 2;            // 0..1 -> t sub-tile
    const int t0     = blockIdx.x << 5;        // 32 t per block
    const int s0     = blockIdx.y << 6;        // 64 s per block
    const int b      = blockIdx.z;

    // ---- phase 1: per-head scores into smem --------------------------------
    for (int h = 0; h < H_; ++h) {
        __syncthreads();   // prior head's MMA reads of Q/K complete
        size_t hb = ((size_t)b * H_ + h) * (S_ * D_);
        // Q tile: 64 rows x 8 chunks, hi+lo -> 2 chunks/thread each
        #pragma unroll
        for (int j = 0; j < 2; ++j) {
            int c    = tid * 2 + j;            // 0..511
            int row  = c >> 3;
            int col8 = (c & 7) * 8;
            size_t g = hb + (size_t)(s0 + row) * 64 + col8;
            int so   = row * 72 + col8;
            *reinterpret_cast<float4*>(sQh + so) = *reinterpret_cast<const float4*>(g_Qh + g);
            *reinterpret_cast<float4*>(sQl + so) = *reinterpret_cast<const float4*>(g_Ql + g);
        }
        // K tile: 32 rows x 8 chunks -> 1 chunk/thread
        {
            int row  = tid >> 3;
            int col8 = (tid & 7) * 8;
            size_t g = hb + (size_t)(t0 + row) * 64 + col8;
            int so   = row * 72 + col8;
            *reinterpret_cast<float4*>(sKh + so) = *reinterpret_cast<const float4*>(g_Kh + g);
            *reinterpret_cast<float4*>(sKl + so) = *reinterpret_cast<const float4*>(g_Kl + g);
        }
        __syncthreads();

        wmma::fragment<wmma::accumulator, 16, 16, 16, float> acc;
        wmma::fill_fragment(acc, 0.0f);
        #pragma unroll
        for (int kk = 0; kk < 4; ++kk) {
            wmma::fragment<wmma::matrix_a, 16, 16, 16, __nv_bfloat16, wmma::row_major> fAh;
            wmma::fragment<wmma::matrix_a, 16, 16, 16, __nv_bfloat16, wmma::row_major> fAl;
            wmma::fragment<wmma::matrix_b, 16, 16, 16, __nv_bfloat16, wmma::col_major> fBh;
            wmma::fragment<wmma::matrix_b, 16, 16, 16, __nv_bfloat16, wmma::col_major> fBl;
            wmma::load_matrix_sync(fAh, sQh + (wmi * 16) * 72 + kk * 16, 72);
            wmma::load_matrix_sync(fAl, sQl + (wmi * 16) * 72 + kk * 16, 72);
            wmma::load_matrix_sync(fBh, sKh + (wnj * 16) * 72 + kk * 16, 72);
            wmma::load_matrix_sync(fBl, sKl + (wnj * 16) * 72 + kk * 16, 72);
            wmma::mma_sync(acc, fAh, fBh, acc);
            wmma::mma_sync(acc, fAh, fBl, acc);
            wmma::mma_sync(acc, fAl, fBh, acc);
        }
        #pragma unroll
        for (int e = 0; e < acc.num_elements; ++e)
            acc.x[e] *= 0.125f;
        wmma::store_matrix_sync(sSc + h * SPLANE + (wmi * 16) * SPAD + wnj * 16,
                                acc, SPAD, wmma::mem_row_major);
    }
    __syncthreads();

    // ---- phase 2: softmax over heads, write bf16 hi/lo ---------------------
    #pragma unroll
    for (int i = 0; i < 8; ++i) {
        int pt = tid + i * 256;                // 0..2047
        int s  = pt >> 5;
        int t  = pt & 31;
        const float* sp = sSc + s * SPAD + t;

        float v[H_];
        float mx = -1e30f;
        #pragma unroll
        for (int h = 0; h < H_; ++h) {
            v[h] = sp[h * SPLANE];
            mx = fmaxf(mx, v[h]);
        }
        float sum = 0.0f;
        #pragma unroll
        for (int h = 0; h < H_; ++h) {
            v[h] = exp_poly(v[h] - mx);
            sum += v[h];
        }
        float inv = __fdividef(1.0f, sum);

        size_t gb = (size_t)b * H_ * ST_ + (size_t)(s0 + s) * S_ + (t0 + t);
        #pragma unroll
        for (int h = 0; h < H_; ++h) {
            float p = v[h] * inv;
            __nv_bfloat16 ph = __float2bfloat16_rn(p);
            __nv_bfloat16 pl = __float2bfloat16_rn(p - __bfloat162float(ph));
            g_Ph[gb + (size_t)h * ST_] = ph;
            g_Pl[gb + (size_t)h * ST_] = pl;
        }
    }
}

// ---------------------------------------------------------------------------
// AV: ctx = P @ V, hi/lo split (unchanged from R10 pass).
// ---------------------------------------------------------------------------
#define AKP       72
#define AV_PT_E   (128 * AKP)
#define AV_VT_E   (64 * AKP)
#define AV_STAGE  (2 * AV_PT_E + 2 * AV_VT_E)
#define AV_SMEM   (2 * AV_STAGE * 2)

__global__ void __launch_bounds__(256)
av_wmma()
{
    extern __shared__ __align__(16) unsigned char smraw[];
    __nv_bfloat16* smb = reinterpret_cast<__nv_bfloat16*>(smraw);

    const int tid    = threadIdx.x;
    const int warpid = tid >> 5;
    const int warpM  = (warpid >> 1) << 5;
    const int warpN  = (warpid & 1) << 5;
    const int blockM = blockIdx.x << 7;
    const int bh     = blockIdx.y;
    const int bE     = bh >> 4;
    const int hE     = bh & 15;

    const __nv_bfloat16* gPh = g_Ph + (size_t)bh * ST_;
    const __nv_bfloat16* gPl = g_Pl + (size_t)bh * ST_;
    const __nv_bfloat16* gVh = g_Vh + (size_t)bh * (S_ * D_);
    const __nv_bfloat16* gVl = g_Vl + (size_t)bh * (S_ * D_);

    const int prow  = tid >> 1;
    const int phalf = tid & 1;
    const int vrow  = tid >> 2;
    const int vcol  = tid & 3;

    wmma::fragment<wmma::accumulator, 16, 16, 16, float> accf[2][2];
    #pragma unroll
    for (int mi = 0; mi < 2; ++mi)
        #pragma unroll
        for (int nj = 0; nj < 2; ++nj)
            wmma::fill_fragment(accf[mi][nj], 0.0f);

    float4 pre[12];
    #pragma unroll
    for (int c = 0; c < 4; ++c) {
        int scol = phalf * 4 + c;
        pre[c * 2 + 0] = *reinterpret_cast<const float4*>(
            gPh + (size_t)(blockM + prow) * S_ + scol * 8);
        pre[c * 2 + 1] = *reinterpret_cast<const float4*>(
            gPl + (size_t)(blockM + prow) * S_ + scol * 8);
    }
    #pragma unroll
    for (int c = 0; c < 2; ++c) {
        int scol = vcol * 2 + c;
        pre[8 + c * 2 + 0] = *reinterpret_cast<const float4*>(
            gVh + (size_t)vrow * 64 + scol * 8);
        pre[8 + c * 2 + 1] = *reinterpret_cast<const float4*>(
            gVl + (size_t)vrow * 64 + scol * 8);
    }

    {
        __nv_bfloat16* st = smb;
        #pragma unroll
        for (int c = 0; c < 4; ++c) {
            int scol = phalf * 4 + c;
            *reinterpret_cast<float4*>(st + prow * AKP + scol * 8) = pre[c * 2 + 0];
            *reinterpret_cast<float4*>(st + AV_PT_E + prow * AKP + scol * 8) = pre[c * 2 + 1];
        }
        #pragma unroll
        for (int c = 0; c < 2; ++c) {
            int scol = vcol * 2 + c;
            *reinterpret_cast<float4*>(st + 2 * AV_PT_E + vrow * AKP + scol * 8) = pre[8 + c * 2 + 0];
            *reinterpret_cast<float4*>(st + 2 * AV_PT_E + AV_VT_E + vrow * AKP + scol * 8) = pre[8 + c * 2 + 1];
        }
    }

    for (int step = 0; step < 32; ++step) {
        if (step < 31) {
            size_t k0 = (size_t)(step + 1) * 64;
            #pragma unroll
            for (int c = 0; c < 4; ++c) {
                int scol = phalf * 4 + c;
                pre[c * 2 + 0] = *reinterpret_cast<const float4*>(
                    gPh + (size_t)(blockM + prow) * S_ + k0 + scol * 8);
                pre[c * 2 + 1] = *reinterpret_cast<const float4*>(
                    gPl + (size_t)(blockM + prow) * S_ + k0 + scol * 8);
            }
            #pragma unroll
            for (int c = 0; c < 2; ++c) {
                int scol = vcol * 2 + c;
                pre[8 + c * 2 + 0] = *reinterpret_cast<const float4*>(
                    gVh + (size_t)(k0 + vrow) * 64 + scol * 8);
                pre[8 + c * 2 + 1] = *reinterpret_cast<const float4*>(
                    gVl + (size_t)(k0 + vrow) * 64 + scol * 8);
            }
        }
        __syncthreads();

        const __nv_bfloat16* st = smb + (step & 1) * AV_STAGE;
        const __nv_bfloat16* sPh = st;
        const __nv_bfloat16* sPl = st + AV_PT_E;
        const __nv_bfloat16* sVh = st + 2 * AV_PT_E;
        const __nv_bfloat16* sVl = st + 2 * AV_PT_E + AV_VT_E;

        #pragma unroll
        for (int kk = 0; kk < 4; ++kk) {
            wmma::fragment<wmma::matrix_a, 16, 16, 16, __nv_bfloat16, wmma::row_major> fAh[2];
            wmma::fragment<wmma::matrix_a, 16, 16, 16, __nv_bfloat16, wmma::row_major> fAl[2];
            wmma::fragment<wmma::matrix_b, 16, 16, 16, __nv_bfloat16, wmma::row_major> fBh[2];
            wmma::fragment<wmma::matrix_b, 16, 16, 16, __nv_bfloat16, wmma::row_major> fBl[2];
            #pragma unroll
            for (int mi = 0; mi < 2; ++mi) {
                wmma::load_matrix_sync(fAh[mi], sPh + (warpM + mi * 16) * AKP + kk * 16, AKP);
                wmma::load_matrix_sync(fAl[mi], sPl + (warpM + mi * 16) * AKP + kk * 16, AKP);
            }
            #pragma unroll
            for (int nj = 0; nj < 2; ++nj) {
                wmma::load_matrix_sync(fBh[nj], sVh + (kk * 16) * AKP + warpN + nj * 16, AKP);
                wmma::load_matrix_sync(fBl[nj], sVl + (kk * 16) * AKP + warpN + nj * 16, AKP);
            }
            #pragma unroll
            for (int mi = 0; mi < 2; ++mi) {
                #pragma unroll
                for (int nj = 0; nj < 2; ++nj) {
                    wmma::mma_sync(accf[mi][nj], fAh[mi], fBh[nj], accf[mi][nj]);
                    wmma::mma_sync(accf[mi][nj], fAh[mi], fBl[nj], accf[mi][nj]);
                    wmma::mma_sync(accf[mi][nj], fAl[mi], fBh[nj], accf[mi][nj]);
                }
            }
        }
        if (step < 31) {
            __nv_bfloat16* nst = smb + ((step + 1) & 1) * AV_STAGE;
            #pragma unroll
            for (int c = 0; c < 4; ++c) {
                int scol = phalf * 4 + c;
                *reinterpret_cast<float4*>(nst + prow * AKP + scol * 8) = pre[c * 2 + 0];
                *reinterpret_cast<float4*>(nst + AV_PT_E + prow * AKP + scol * 8) = pre[c * 2 + 1];
            }
            #pragma unroll
            for (int c = 0; c < 2; ++c) {
                int scol = vcol * 2 + c;
                *reinterpret_cast<float4*>(nst + 2 * AV_PT_E + vrow * AKP + scol * 8) = pre[8 + c * 2 + 0];
                *reinterpret_cast<float4*>(nst + 2 * AV_PT_E + AV_VT_E + vrow * AKP + scol * 8) = pre[8 + c * 2 + 1];
            }
        }
    }

    #pragma unroll
    for (int mi = 0; mi < 2; ++mi) {
        #pragma unroll
        for (int nj = 0; nj < 2; ++nj) {
            float* pd = g_ctx + (size_t)(blockM + warpM + mi * 16) * (B_ * E_)
                      + (size_t)bE * E_ + hE * 64 + warpN + nj * 16;
            wmma::store_matrix_sync(pd, accf[mi][nj], B_ * E_, wmma::mem_row_major);
        }
    }
}

// ---------------------------------------------------------------------------
// Launch. Inputs (metadata order): x, Wq, bq, Wk, bk, Wv, bv, Wo, bo
// ---------------------------------------------------------------------------
extern "C" void kernel_launch(void* const* d_in, const int* in_sizes, int n_in,
                              void* d_out, int out_size)
{
    const float* x  = (const float*)d_in[0];
    const float* Wq = (const float*)d_in[1];
    const float* bq = (const float*)d_in[2];
    const float* Wk = (const float*)d_in[3];
    const float* bk = (const float*)d_in[4];
    const float* Wv = (const float*)d_in[5];
    const float* bv = (const float*)d_in[6];
    const float* Wo = (const float*)d_in[7];
    const float* bo = (const float*)d_in[8];
    float* out = (float*)d_out;

    cudaFuncSetAttribute(wmma_gemm,
                         cudaFuncAttributeMaxDynamicSharedMemorySize, GEMM_SMEM);
    cudaFuncSetAttribute(scores_softmax,
                         cudaFuncAttributeMaxDynamicSharedMemorySize, SS_SMEM);
    cudaFuncSetAttribute(av_wmma,
                         cudaFuncAttributeMaxDynamicSharedMemorySize, AV_SMEM);

    __nv_bfloat16* xh;
    __nv_bfloat16* xl;
    __nv_bfloat16* Wh;
    __nv_bfloat16* Wl;
    __nv_bfloat16* ch;
    __nv_bfloat16* cl;
    float* ctxp;
    cudaGetSymbolAddress((void**)&xh, g_xh);
    cudaGetSymbolAddress((void**)&xl, g_xl);
    cudaGetSymbolAddress((void**)&Wh, g_Wh);
    cudaGetSymbolAddress((void**)&Wl, g_Wl);
    cudaGetSymbolAddress((void**)&ch, g_ch);
    cudaGetSymbolAddress((void**)&cl, g_cl);
    cudaGetSymbolAddress((void**)&ctxp, g_ctx);

    const size_t WSZ = (size_t)E_ * E_;
    dim3 blk(256);

    conv_split<<<(M_ * E_ / 4 + 255) / 256, blk>>>(x,  xh, xl, M_ * E_ / 4);
    conv_split<<<(WSZ / 4 + 255) / 256, blk>>>(Wq, Wh + 0 * WSZ, Wl + 0 * WSZ, WSZ / 4);
    conv_split<<<(WSZ / 4 + 255) / 256, blk>>>(Wk, Wh + 1 * WSZ, Wl + 1 * WSZ, WSZ / 4);
    conv_split<<<(WSZ / 4 + 255) / 256, blk>>>(Wv, Wh + 2 * WSZ, Wl + 2 * WSZ, WSZ / 4);
    conv_split<<<(WSZ / 4 + 255) / 256, blk>>>(Wo, Wh + 3 * WSZ, Wl + 3 * WSZ, WSZ / 4);

    dim3 gGemm(E_ / 128, M_ / 128);
    wmma_gemm<<<gGemm, blk, GEMM_SMEM>>>(xh, xl, Wh + 0 * WSZ, Wl + 0 * WSZ,
                                         bq, nullptr, 0);
    wmma_gemm<<<gGemm, blk, GEMM_SMEM>>>(xh, xl, Wh + 1 * WSZ, Wl + 1 * WSZ,
                                         bk, nullptr, 1);
    wmma_gemm<<<gGemm, blk, GEMM_SMEM>>>(xh, xl, Wh + 2 * WSZ, Wl + 2 * WSZ,
                                         bv, nullptr, 2);

    scores_softmax<<<dim3(S_ / SS_T, S_ / SS_S, B_), blk, SS_SMEM>>>();
    av_wmma<<<dim3(S_ / 128, BHn), blk, AV_SMEM>>>();

    conv_split<<<(M_ * E_ / 4 + 255) / 256, blk>>>(ctxp, ch, cl, M_ * E_ / 4);
    wmma_gemm<<<gGemm, blk, GEMM_SMEM>>>(ch, cl, Wh + 3 * WSZ, Wl + 3 * WSZ,
                                         bo, out, 3);
}

// round 13
// speedup vs baseline: 1.1996x; 1.1996x over previous
#include <cuda_runtime.h>
#include <cuda_bf16.h>
#include <mma.h>
#include <math.h>

// ---------------------------------------------------------------------------
// Problem dims (fixed)
// ---------------------------------------------------------------------------
#define S_  2048
#define B_  2
#define E_  1024
#define H_  16
#define D_  64
#define M_  (S_ * B_)
#define BHn (B_ * H_)
#define ST_ ((size_t)S_ * S_)

// ---------------------------------------------------------------------------
// Device scratch (static). ~1.2 GB total.
// ---------------------------------------------------------------------------
__device__ __align__(128) __nv_bfloat16 g_Qh[(size_t)BHn * S_ * D_];
__device__ __align__(128) __nv_bfloat16 g_Ql[(size_t)BHn * S_ * D_];
__device__ __align__(128) __nv_bfloat16 g_Kh[(size_t)BHn * S_ * D_];
__device__ __align__(128) __nv_bfloat16 g_Kl[(size_t)BHn * S_ * D_];
__device__ __align__(128) __nv_bfloat16 g_Vh[(size_t)BHn * S_ * D_];
__device__ __align__(128) __nv_bfloat16 g_Vl[(size_t)BHn * S_ * D_];
__device__ float g_P[(size_t)BHn * ST_];                 // fp32 scores 512 MB
__device__ __align__(128) __nv_bfloat16 g_Ph[(size_t)BHn * ST_];
__device__ __align__(128) __nv_bfloat16 g_Pl[(size_t)BHn * ST_];
__device__ float g_ctx[(size_t)M_ * E_];

__device__ __align__(128) __nv_bfloat16 g_xh[(size_t)M_ * E_];
__device__ __align__(128) __nv_bfloat16 g_xl[(size_t)M_ * E_];
__device__ __align__(128) __nv_bfloat16 g_Wh[(size_t)4 * E_ * E_];
__device__ __align__(128) __nv_bfloat16 g_Wl[(size_t)4 * E_ * E_];
__device__ __align__(128) __nv_bfloat16 g_ch[(size_t)M_ * E_];
__device__ __align__(128) __nv_bfloat16 g_cl[(size_t)M_ * E_];

using namespace nvcuda;

// ---------------------------------------------------------------------------
// Split fp32 -> bf16 hi + bf16 lo (residual). Vectorized by 4.
// ---------------------------------------------------------------------------
__global__ void __launch_bounds__(256)
conv_split(const float* __restrict__ src, __nv_bfloat16* __restrict__ hi,
           __nv_bfloat16* __restrict__ lo, int n4)
{
    int idx = blockIdx.x * 256 + threadIdx.x;
    if (idx >= n4) return;
    float4 vin = reinterpret_cast<const float4*>(src)[idx];
    float vals[4];
    vals[0] = vin.x; vals[1] = vin.y; vals[2] = vin.z; vals[3] = vin.w;
    __nv_bfloat16 hiv[4];
    __nv_bfloat16 lov[4];
    #pragma unroll
    for (int j = 0; j < 4; ++j) {
        hiv[j] = __float2bfloat16_rn(vals[j]);
        lov[j] = __float2bfloat16_rn(vals[j] - __bfloat162float(hiv[j]));
    }
    __nv_bfloat162* hp = reinterpret_cast<__nv_bfloat162*>(hi);
    __nv_bfloat162* lp = reinterpret_cast<__nv_bfloat162*>(lo);
    hp[2 * idx + 0] = __nv_bfloat162(hiv[0], hiv[1]);
    hp[2 * idx + 1] = __nv_bfloat162(hiv[2], hiv[3]);
    lp[2 * idx + 0] = __nv_bfloat162(lov[0], lov[1]);
    lp[2 * idx + 1] = __nv_bfloat162(lov[2], lov[3]);
}

// ---------------------------------------------------------------------------
// WMMA projection GEMM (unchanged from R10 pass). BM=BN=128, BK=32,
// 2-stage smem + register prefetch, 3-product hi/lo split.
// mode 0/1/2: write bf16 hi/lo Q/K/V [b][h][s][d]; mode 3: fp32 outp[m][n].
// ---------------------------------------------------------------------------
#define SKP        40
#define TILE_E     (128 * SKP)
#define STAGE_E    (4 * TILE_E)
#define GEMM_SMEM  (2 * STAGE_E * 2)

__global__ void __launch_bounds__(256)
wmma_gemm(const __nv_bfloat16* __restrict__ Ahp, const __nv_bfloat16* __restrict__ Alp,
          const __nv_bfloat16* __restrict__ Whp, const __nv_bfloat16* __restrict__ Wlp,
          const float* __restrict__ bias, float* __restrict__ outp, int mode)
{
    extern __shared__ __align__(16) unsigned char smraw[];
    __nv_bfloat16* smb = reinterpret_cast<__nv_bfloat16*>(smraw);

    const int tid    = threadIdx.x;
    const int lane   = tid & 31;
    const int warpid = tid >> 5;
    const int warpM  = (warpid >> 2) << 6;
    const int warpN  = (warpid & 3) << 5;
    const int blockM = blockIdx.y << 7;
    const int blockN = blockIdx.x << 7;

    const __nv_bfloat16* gT[4];
    gT[0] = Ahp + (size_t)blockM * 1024;
    gT[1] = Alp + (size_t)blockM * 1024;
    gT[2] = Whp + (size_t)blockN * 1024;
    gT[3] = Wlp + (size_t)blockN * 1024;

    const int srow  = tid >> 1;
    const int shalf = tid & 1;

    wmma::fragment<wmma::accumulator, 16, 16, 16, float> accf[4][2];
    #pragma unroll
    for (int mi = 0; mi < 4; ++mi)
        #pragma unroll
        for (int nj = 0; nj < 2; ++nj)
            wmma::fill_fragment(accf[mi][nj], 0.0f);

    float4 pre[8];
    #pragma unroll
    for (int t = 0; t < 4; ++t)
        #pragma unroll
        for (int c = 0; c < 2; ++c)
            pre[t * 2 + c] = *reinterpret_cast<const float4*>(
                gT[t] + (size_t)srow * 1024 + (size_t)(shalf * 2 + c) * 8);
    #pragma unroll
    for (int t = 0; t < 4; ++t)
        #pragma unroll
        for (int c = 0; c < 2; ++c)
            *reinterpret_cast<float4*>(
                smb + t * TILE_E + srow * SKP + (shalf * 2 + c) * 8) = pre[t * 2 + c];

    for (int step = 0; step < 32; ++step) {
        if (step < 31) {
            size_t k0 = (size_t)(step + 1) * 32;
            #pragma unroll
            for (int t = 0; t < 4; ++t)
                #pragma unroll
                for (int c = 0; c < 2; ++c)
                    pre[t * 2 + c] = *reinterpret_cast<const float4*>(
                        gT[t] + (size_t)srow * 1024 + k0 + (size_t)(shalf * 2 + c) * 8);
        }
        __syncthreads();

        const __nv_bfloat16* stg = smb + (step & 1) * STAGE_E;
        #pragma unroll
        for (int kk = 0; kk < 2; ++kk) {
            wmma::fragment<wmma::matrix_a, 16, 16, 16, __nv_bfloat16, wmma::row_major> fAh[4];
            wmma::fragment<wmma::matrix_a, 16, 16, 16, __nv_bfloat16, wmma::row_major> fAl[4];
            wmma::fragment<wmma::matrix_b, 16, 16, 16, __nv_bfloat16, wmma::col_major> fBh[2];
            wmma::fragment<wmma::matrix_b, 16, 16, 16, __nv_bfloat16, wmma::col_major> fBl[2];
            #pragma unroll
            for (int mi = 0; mi < 4; ++mi) {
                wmma::load_matrix_sync(fAh[mi],
                    stg + 0 * TILE_E + (warpM + mi * 16) * SKP + kk * 16, SKP);
                wmma::load_matrix_sync(fAl[mi],
                    stg + 1 * TILE_E + (warpM + mi * 16) * SKP + kk * 16, SKP);
            }
            #pragma unroll
            for (int nj = 0; nj < 2; ++nj) {
                wmma::load_matrix_sync(fBh[nj],
                    stg + 2 * TILE_E + (warpN + nj * 16) * SKP + kk * 16, SKP);
                wmma::load_matrix_sync(fBl[nj],
                    stg + 3 * TILE_E + (warpN + nj * 16) * SKP + kk * 16, SKP);
            }
            #pragma unroll
            for (int mi = 0; mi < 4; ++mi) {
                #pragma unroll
                for (int nj = 0; nj < 2; ++nj) {
                    wmma::mma_sync(accf[mi][nj], fAh[mi], fBh[nj], accf[mi][nj]);
                    wmma::mma_sync(accf[mi][nj], fAh[mi], fBl[nj], accf[mi][nj]);
                    wmma::mma_sync(accf[mi][nj], fAl[mi], fBh[nj], accf[mi][nj]);
                }
            }
        }
        if (step < 31) {
            __nv_bfloat16* nstg = smb + ((step + 1) & 1) * STAGE_E;
            #pragma unroll
            for (int t = 0; t < 4; ++t)
                #pragma unroll
                for (int c = 0; c < 2; ++c)
                    *reinterpret_cast<float4*>(
                        nstg + t * TILE_E + srow * SKP + (shalf * 2 + c) * 8) = pre[t * 2 + c];
        }
    }

    __syncthreads();
    float* stgf = reinterpret_cast<float*>(smraw) + warpid * 576;

    __nv_bfloat16* dsth = (mode == 0) ? g_Qh : (mode == 1) ? g_Kh : g_Vh;
    __nv_bfloat16* dstl = (mode == 0) ? g_Ql : (mode == 1) ? g_Kl : g_Vl;

    const int erow = lane >> 1;
    const int ecol = (lane & 1) * 16;

    #pragma unroll
    for (int mi = 0; mi < 4; ++mi) {
        wmma::store_matrix_sync(stgf + 0,  accf[mi][0], 36, wmma::mem_row_major);
        wmma::store_matrix_sync(stgf + 16, accf[mi][1], 36, wmma::mem_row_major);
        __syncwarp();

        int mRow = blockM + warpM + mi * 16 + erow;
        int col0 = blockN + warpN + ecol;

        float vv[16];
        #pragma unroll
        for (int c = 0; c < 4; ++c) {
            float4 t4 = *reinterpret_cast<const float4*>(stgf + erow * 36 + ecol + c * 4);
            float4 b4 = *reinterpret_cast<const float4*>(bias + col0 + c * 4);
            vv[c * 4 + 0] = t4.x + b4.x;
            vv[c * 4 + 1] = t4.y + b4.y;
            vv[c * 4 + 2] = t4.z + b4.z;
            vv[c * 4 + 3] = t4.w + b4.w;
        }

        if (mode <= 2) {
            int sE = mRow >> 1;
            int bE = mRow & 1;
            int hE = col0 >> 6;
            int dE = col0 & 63;
            unsigned int pwh[8];
            unsigned int pwl[8];
            #pragma unroll
            for (int j = 0; j < 8; ++j) {
                __nv_bfloat16 h0 = __float2bfloat16_rn(vv[2 * j]);
                __nv_bfloat16 h1 = __float2bfloat16_rn(vv[2 * j + 1]);
                __nv_bfloat16 l0 = __float2bfloat16_rn(vv[2 * j] - __bfloat162float(h0));
                __nv_bfloat16 l1 = __float2bfloat16_rn(vv[2 * j + 1] - __bfloat162float(h1));
                pwh[j] = (unsigned int)__bfloat16_as_ushort(h0)
                       | ((unsigned int)__bfloat16_as_ushort(h1) << 16);
                pwl[j] = (unsigned int)__bfloat16_as_ushort(l0)
                       | ((unsigned int)__bfloat16_as_ushort(l1) << 16);
            }
            size_t base = ((((size_t)bE * H_ + hE) * S_ + sE) << 6) + dE;
            uint4* ph = reinterpret_cast<uint4*>(dsth + base);
            uint4* pl = reinterpret_cast<uint4*>(dstl + base);
            ph[0] = make_uint4(pwh[0], pwh[1], pwh[2], pwh[3]);
            ph[1] = make_uint4(pwh[4], pwh[5], pwh[6], pwh[7]);
            pl[0] = make_uint4(pwl[0], pwl[1], pwl[2], pwl[3]);
            pl[1] = make_uint4(pwl[4], pwl[5], pwl[6], pwl[7]);
        } else {
            float* pd = outp + (size_t)mRow * 1024 + col0;
            #pragma unroll
            for (int c = 0; c < 4; ++c)
                *reinterpret_cast<float4*>(pd + c * 4)
                    = make_float4(vv[c*4+0], vv[c*4+1], vv[c*4+2], vv[c*4+3]);
        }
        __syncwarp();
    }
}

// ---------------------------------------------------------------------------
// Scores: P[bh][s][t] = (Q_bh . K_bh^T) / 8, bf16 hi/lo 3-product split.
// BM=BN=128, K=64 one-shot. (Unchanged from R10 pass.)
// ---------------------------------------------------------------------------
#define AKP        72
#define SC_TILE_E  (128 * AKP)
#define SC_SMEM    (4 * SC_TILE_E * 2)

__global__ void __launch_bounds__(256)
scores_wmma()
{
    extern __shared__ __align__(16) unsigned char smraw[];
    __nv_bfloat16* smb = reinterpret_cast<__nv_bfloat16*>(smraw);
    __nv_bfloat16* sQh = smb;
    __nv_bfloat16* sQl = smb + SC_TILE_E;
    __nv_bfloat16* sKh = smb + 2 * SC_TILE_E;
    __nv_bfloat16* sKl = smb + 3 * SC_TILE_E;

    const int tid    = threadIdx.x;
    const int warpid = tid >> 5;
    const int warpM  = (warpid >> 2) << 6;
    const int warpN  = (warpid & 3) << 5;
    const int blockM = blockIdx.y << 7;
    const int blockN = blockIdx.x << 7;
    const int bh     = blockIdx.z;

    const size_t qoff = (size_t)bh * (S_ * D_);
    const int srow  = tid >> 1;
    const int shalf = tid & 1;

    #pragma unroll
    for (int c = 0; c < 4; ++c) {
        int scol = shalf * 4 + c;
        size_t gq = qoff + (size_t)(blockM + srow) * 64 + scol * 8;
        size_t gk = qoff + (size_t)(blockN + srow) * 64 + scol * 8;
        int so = srow * AKP + scol * 8;
        *reinterpret_cast<float4*>(sQh + so) = *reinterpret_cast<const float4*>(g_Qh + gq);
        *reinterpret_cast<float4*>(sQl + so) = *reinterpret_cast<const float4*>(g_Ql + gq);
        *reinterpret_cast<float4*>(sKh + so) = *reinterpret_cast<const float4*>(g_Kh + gk);
        *reinterpret_cast<float4*>(sKl + so) = *reinterpret_cast<const float4*>(g_Kl + gk);
    }
    __syncthreads();

    wmma::fragment<wmma::accumulator, 16, 16, 16, float> accf[4][2];
    #pragma unroll
    for (int mi = 0; mi < 4; ++mi)
        #pragma unroll
        for (int nj = 0; nj < 2; ++nj)
            wmma::fill_fragment(accf[mi][nj], 0.0f);

    #pragma unroll
    for (int kk = 0; kk < 4; ++kk) {
        wmma::fragment<wmma::matrix_a, 16, 16, 16, __nv_bfloat16, wmma::row_major> fAh[4];
        wmma::fragment<wmma::matrix_a, 16, 16, 16, __nv_bfloat16, wmma::row_major> fAl[4];
        wmma::fragment<wmma::matrix_b, 16, 16, 16, __nv_bfloat16, wmma::col_major> fBh[2];
        wmma::fragment<wmma::matrix_b, 16, 16, 16, __nv_bfloat16, wmma::col_major> fBl[2];
        #pragma unroll
        for (int mi = 0; mi < 4; ++mi) {
            wmma::load_matrix_sync(fAh[mi], sQh + (warpM + mi * 16) * AKP + kk * 16, AKP);
            wmma::load_matrix_sync(fAl[mi], sQl + (warpM + mi * 16) * AKP + kk * 16, AKP);
        }
        #pragma unroll
        for (int nj = 0; nj < 2; ++nj) {
            wmma::load_matrix_sync(fBh[nj], sKh + (warpN + nj * 16) * AKP + kk * 16, AKP);
            wmma::load_matrix_sync(fBl[nj], sKl + (warpN + nj * 16) * AKP + kk * 16, AKP);
        }
        #pragma unroll
        for (int mi = 0; mi < 4; ++mi) {
            #pragma unroll
            for (int nj = 0; nj < 2; ++nj) {
                wmma::mma_sync(accf[mi][nj], fAh[mi], fBh[nj], accf[mi][nj]);
                wmma::mma_sync(accf[mi][nj], fAh[mi], fBl[nj], accf[mi][nj]);
                wmma::mma_sync(accf[mi][nj], fAl[mi], fBh[nj], accf[mi][nj]);
            }
        }
    }

    float* pb = g_P + (size_t)bh * ST_;
    #pragma unroll
    for (int mi = 0; mi < 4; ++mi) {
        #pragma unroll
        for (int nj = 0; nj < 2; ++nj) {
            #pragma unroll
            for (int e = 0; e < accf[mi][nj].num_elements; ++e)
                accf[mi][nj].x[e] *= 0.125f;
            wmma::store_matrix_sync(
                pb + (size_t)(blockM + warpM + mi * 16) * S_ + blockN + warpN + nj * 16,
                accf[mi][nj], S_, wmma::mem_row_major);
        }
    }
}

// ---------------------------------------------------------------------------
// Softmax over HEADS, VECTORIZED: 4 consecutive t per thread.
// float4 plane loads, uint2 (bf16x4) packed stores. Math identical to R10.
// ---------------------------------------------------------------------------
__device__ __forceinline__ float exp_poly(float x)
{
    float t = x * 1.4426950408889634f;
    t = fmaxf(t, -80.0f);
    float fi = floorf(t);
    float f = t - fi;
    float p = 0.0001540353f;
    p = p * f + 0.0013333558f;
    p = p * f + 0.0096181291f;
    p = p * f + 0.0555041087f;
    p = p * f + 0.2402265069f;
    p = p * f + 0.6931471806f;
    p = p * f + 1.0f;
    int ei = (int)fi + 127;
    float sc = __uint_as_float(((unsigned int)ei) << 23);
    return p * sc;
}

__global__ void __launch_bounds__(256)
softmax_heads()
{
    size_t id = (size_t)blockIdx.x * 256 + threadIdx.x;   // B*S*S/4 threads
    int t4 = (int)(id & 511);            // t / 4
    int s  = (int)((id >> 9) & 2047);
    int b  = (int)(id >> 20);

    size_t base = (size_t)b * H_ * ST_ + (size_t)s * S_ + (size_t)t4 * 4;

    float4 v[H_];
    float4 mx = make_float4(-1e30f, -1e30f, -1e30f, -1e30f);
    #pragma unroll
    for (int h = 0; h < H_; ++h) {
        v[h] = *reinterpret_cast<const float4*>(g_P + base + (size_t)h * ST_);
        mx.x = fmaxf(mx.x, v[h].x);
        mx.y = fmaxf(mx.y, v[h].y);
        mx.z = fmaxf(mx.z, v[h].z);
        mx.w = fmaxf(mx.w, v[h].w);
    }
    float4 sum = make_float4(0.f, 0.f, 0.f, 0.f);
    #pragma unroll
    for (int h = 0; h < H_; ++h) {
        v[h].x = exp_poly(v[h].x - mx.x);
        v[h].y = exp_poly(v[h].y - mx.y);
        v[h].z = exp_poly(v[h].z - mx.z);
        v[h].w = exp_poly(v[h].w - mx.w);
        sum.x += v[h].x;
        sum.y += v[h].y;
        sum.z += v[h].z;
        sum.w += v[h].w;
    }
    float4 inv;
    inv.x = __fdividef(1.0f, sum.x);
    inv.y = __fdividef(1.0f, sum.y);
    inv.z = __fdividef(1.0f, sum.z);
    inv.w = __fdividef(1.0f, sum.w);

    #pragma unroll
    for (int h = 0; h < H_; ++h) {
        float p0 = v[h].x * inv.x;
        float p1 = v[h].y * inv.y;
        float p2 = v[h].z * inv.z;
        float p3 = v[h].w * inv.w;
        __nv_bfloat16 h0 = __float2bfloat16_rn(p0);
        __nv_bfloat16 h1 = __float2bfloat16_rn(p1);
        __nv_bfloat16 h2 = __float2bfloat16_rn(p2);
        __nv_bfloat16 h3 = __float2bfloat16_rn(p3);
        __nv_bfloat16 l0 = __float2bfloat16_rn(p0 - __bfloat162float(h0));
        __nv_bfloat16 l1 = __float2bfloat16_rn(p1 - __bfloat162float(h1));
        __nv_bfloat16 l2 = __float2bfloat16_rn(p2 - __bfloat162float(h2));
        __nv_bfloat16 l3 = __float2bfloat16_rn(p3 - __bfloat162float(h3));
        uint2 wh;
        wh.x = (unsigned int)__bfloat16_as_ushort(h0)
             | ((unsigned int)__bfloat16_as_ushort(h1) << 16);
        wh.y = (unsigned int)__bfloat16_as_ushort(h2)
             | ((unsigned int)__bfloat16_as_ushort(h3) << 16);
        uint2 wl;
        wl.x = (unsigned int)__bfloat16_as_ushort(l0)
             | ((unsigned int)__bfloat16_as_ushort(l1) << 16);
        wl.y = (unsigned int)__bfloat16_as_ushort(l2)
             | ((unsigned int)__bfloat16_as_ushort(l3) << 16);
        *reinterpret_cast<uint2*>(g_Ph + base + (size_t)h * ST_) = wh;
        *reinterpret_cast<uint2*>(g_Pl + base + (size_t)h * ST_) = wl;
    }
}

// ---------------------------------------------------------------------------
// AV: ctx = P @ V, hi/lo split (unchanged from R10 pass).
// ---------------------------------------------------------------------------
#define AV_PT_E   (128 * AKP)
#define AV_VT_E   (64 * AKP)
#define AV_STAGE  (2 * AV_PT_E + 2 * AV_VT_E)
#define AV_SMEM   (2 * AV_STAGE * 2)

__global__ void __launch_bounds__(256)
av_wmma()
{
    extern __shared__ __align__(16) unsigned char smraw[];
    __nv_bfloat16* smb = reinterpret_cast<__nv_bfloat16*>(smraw);

    const int tid    = threadIdx.x;
    const int warpid = tid >> 5;
    const int warpM  = (warpid >> 1) << 5;
    const int warpN  = (warpid & 1) << 5;
    const int blockM = blockIdx.x << 7;
    const int bh     = blockIdx.y;
    const int bE     = bh >> 4;
    const int hE     = bh & 15;

    const __nv_bfloat16* gPh = g_Ph + (size_t)bh * ST_;
    const __nv_bfloat16* gPl = g_Pl + (size_t)bh * ST_;
    const __nv_bfloat16* gVh = g_Vh + (size_t)bh * (S_ * D_);
    const __nv_bfloat16* gVl = g_Vl + (size_t)bh * (S_ * D_);

    const int prow  = tid >> 1;
    const int phalf = tid & 1;
    const int vrow  = tid >> 2;
    const int vcol  = tid & 3;

    wmma::fragment<wmma::accumulator, 16, 16, 16, float> accf[2][2];
    #pragma unroll
    for (int mi = 0; mi < 2; ++mi)
        #pragma unroll
        for (int nj = 0; nj < 2; ++nj)
            wmma::fill_fragment(accf[mi][nj], 0.0f);

    float4 pre[12];
    #pragma unroll
    for (int c = 0; c < 4; ++c) {
        int scol = phalf * 4 + c;
        pre[c * 2 + 0] = *reinterpret_cast<const float4*>(
            gPh + (size_t)(blockM + prow) * S_ + scol * 8);
        pre[c * 2 + 1] = *reinterpret_cast<const float4*>(
            gPl + (size_t)(blockM + prow) * S_ + scol * 8);
    }
    #pragma unroll
    for (int c = 0; c < 2; ++c) {
        int scol = vcol * 2 + c;
        pre[8 + c * 2 + 0] = *reinterpret_cast<const float4*>(
            gVh + (size_t)vrow * 64 + scol * 8);
        pre[8 + c * 2 + 1] = *reinterpret_cast<const float4*>(
            gVl + (size_t)vrow * 64 + scol * 8);
    }

    {
        __nv_bfloat16* st = smb;
        #pragma unroll
        for (int c = 0; c < 4; ++c) {
            int scol = phalf * 4 + c;
            *reinterpret_cast<float4*>(st + prow * AKP + scol * 8) = pre[c * 2 + 0];
            *reinterpret_cast<float4*>(st + AV_PT_E + prow * AKP + scol * 8) = pre[c * 2 + 1];
        }
        #pragma unroll
        for (int c = 0; c < 2; ++c) {
            int scol = vcol * 2 + c;
            *reinterpret_cast<float4*>(st + 2 * AV_PT_E + vrow * AKP + scol * 8) = pre[8 + c * 2 + 0];
            *reinterpret_cast<float4*>(st + 2 * AV_PT_E + AV_VT_E + vrow * AKP + scol * 8) = pre[8 + c * 2 + 1];
        }
    }

    for (int step = 0; step < 32; ++step) {
        if (step < 31) {
            size_t k0 = (size_t)(step + 1) * 64;
            #pragma unroll
            for (int c = 0; c < 4; ++c) {
                int scol = phalf * 4 + c;
                pre[c * 2 + 0] = *reinterpret_cast<const float4*>(
                    gPh + (size_t)(blockM + prow) * S_ + k0 + scol * 8);
                pre[c * 2 + 1] = *reinterpret_cast<const float4*>(
                    gPl + (size_t)(blockM + prow) * S_ + k0 + scol * 8);
            }
            #pragma unroll
            for (int c = 0; c < 2; ++c) {
                int scol = vcol * 2 + c;
                pre[8 + c * 2 + 0] = *reinterpret_cast<const float4*>(
                    gVh + (size_t)(k0 + vrow) * 64 + scol * 8);
                pre[8 + c * 2 + 1] = *reinterpret_cast<const float4*>(
                    gVl + (size_t)(k0 + vrow) * 64 + scol * 8);
            }
        }
        __syncthreads();

        const __nv_bfloat16* st = smb + (step & 1) * AV_STAGE;
        const __nv_bfloat16* sPh = st;
        const __nv_bfloat16* sPl = st + AV_PT_E;
        const __nv_bfloat16* sVh = st + 2 * AV_PT_E;
        const __nv_bfloat16* sVl = st + 2 * AV_PT_E + AV_VT_E;

        #pragma unroll
        for (int kk = 0; kk < 4; ++kk) {
            wmma::fragment<wmma::matrix_a, 16, 16, 16, __nv_bfloat16, wmma::row_major> fAh[2];
            wmma::fragment<wmma::matrix_a, 16, 16, 16, __nv_bfloat16, wmma::row_major> fAl[2];
            wmma::fragment<wmma::matrix_b, 16, 16, 16, __nv_bfloat16, wmma::row_major> fBh[2];
            wmma::fragment<wmma::matrix_b, 16, 16, 16, __nv_bfloat16, wmma::row_major> fBl[2];
            #pragma unroll
            for (int mi = 0; mi < 2; ++mi) {
                wmma::load_matrix_sync(fAh[mi], sPh + (warpM + mi * 16) * AKP + kk * 16, AKP);
                wmma::load_matrix_sync(fAl[mi], sPl + (warpM + mi * 16) * AKP + kk * 16, AKP);
            }
            #pragma unroll
            for (int nj = 0; nj < 2; ++nj) {
                wmma::load_matrix_sync(fBh[nj], sVh + (kk * 16) * AKP + warpN + nj * 16, AKP);
                wmma::load_matrix_sync(fBl[nj], sVl + (kk * 16) * AKP + warpN + nj * 16, AKP);
            }
            #pragma unroll
            for (int mi = 0; mi < 2; ++mi) {
                #pragma unroll
                for (int nj = 0; nj < 2; ++nj) {
                    wmma::mma_sync(accf[mi][nj], fAh[mi], fBh[nj], accf[mi][nj]);
                    wmma::mma_sync(accf[mi][nj], fAh[mi], fBl[nj], accf[mi][nj]);
                    wmma::mma_sync(accf[mi][nj], fAl[mi], fBh[nj], accf[mi][nj]);
                }
            }
        }
        if (step < 31) {
            __nv_bfloat16* nst = smb + ((step + 1) & 1) * AV_STAGE;
            #pragma unroll
            for (int c = 0; c < 4; ++c) {
                int scol = phalf * 4 + c;
                *reinterpret_cast<float4*>(nst + prow * AKP + scol * 8) = pre[c * 2 + 0];
                *reinterpret_cast<float4*>(nst + AV_PT_E + prow * AKP + scol * 8) = pre[c * 2 + 1];
            }
            #pragma unroll
            for (int c = 0; c < 2; ++c) {
                int scol = vcol * 2 + c;
                *reinterpret_cast<float4*>(nst + 2 * AV_PT_E + vrow * AKP + scol * 8) = pre[8 + c * 2 + 0];
                *reinterpret_cast<float4*>(nst + 2 * AV_PT_E + AV_VT_E + vrow * AKP + scol * 8) = pre[8 + c * 2 + 1];
            }
        }
    }

    #pragma unroll
    for (int mi = 0; mi < 2; ++mi) {
        #pragma unroll
        for (int nj = 0; nj < 2; ++nj) {
            float* pd = g_ctx + (size_t)(blockM + warpM + mi * 16) * (B_ * E_)
                      + (size_t)bE * E_ + hE * 64 + warpN + nj * 16;
            wmma::store_matrix_sync(pd, accf[mi][nj], B_ * E_, wmma::mem_row_major);
        }
    }
}

// ---------------------------------------------------------------------------
// Launch. Inputs (metadata order): x, Wq, bq, Wk, bk, Wv, bv, Wo, bo
// ---------------------------------------------------------------------------
extern "C" void kernel_launch(void* const* d_in, const int* in_sizes, int n_in,
                              void* d_out, int out_size)
{
    const float* x  = (const float*)d_in[0];
    const float* Wq = (const float*)d_in[1];
    const float* bq = (const float*)d_in[2];
    const float* Wk = (const float*)d_in[3];
    const float* bk = (const float*)d_in[4];
    const float* Wv = (const float*)d_in[5];
    const float* bv = (const float*)d_in[6];
    const float* Wo = (const float*)d_in[7];
    const float* bo = (const float*)d_in[8];
    float* out = (float*)d_out;

    cudaFuncSetAttribute(wmma_gemm,
                         cudaFuncAttributeMaxDynamicSharedMemorySize, GEMM_SMEM);
    cudaFuncSetAttribute(scores_wmma,
                         cudaFuncAttributeMaxDynamicSharedMemorySize, SC_SMEM);
    cudaFuncSetAttribute(av_wmma,
                         cudaFuncAttributeMaxDynamicSharedMemorySize, AV_SMEM);

    __nv_bfloat16* xh;
    __nv_bfloat16* xl;
    __nv_bfloat16* Wh;
    __nv_bfloat16* Wl;
    __nv_bfloat16* ch;
    __nv_bfloat16* cl;
    float* ctxp;
    cudaGetSymbolAddress((void**)&xh, g_xh);
    cudaGetSymbolAddress((void**)&xl, g_xl);
    cudaGetSymbolAddress((void**)&Wh, g_Wh);
    cudaGetSymbolAddress((void**)&Wl, g_Wl);
    cudaGetSymbolAddress((void**)&ch, g_ch);
    cudaGetSymbolAddress((void**)&cl, g_cl);
    cudaGetSymbolAddress((void**)&ctxp, g_ctx);

    const size_t WSZ = (size_t)E_ * E_;
    dim3 blk(256);

    conv_split<<<(M_ * E_ / 4 + 255) / 256, blk>>>(x,  xh, xl, M_ * E_ / 4);
    conv_split<<<(WSZ / 4 + 255) / 256, blk>>>(Wq, Wh + 0 * WSZ, Wl + 0 * WSZ, WSZ / 4);
    conv_split<<<(WSZ / 4 + 255) / 256, blk>>>(Wk, Wh + 1 * WSZ, Wl + 1 * WSZ, WSZ / 4);
    conv_split<<<(WSZ / 4 + 255) / 256, blk>>>(Wv, Wh + 2 * WSZ, Wl + 2 * WSZ, WSZ / 4);
    conv_split<<<(WSZ / 4 + 255) / 256, blk>>>(Wo, Wh + 3 * WSZ, Wl + 3 * WSZ, WSZ / 4);

    dim3 gGemm(E_ / 128, M_ / 128);
    wmma_gemm<<<gGemm, blk, GEMM_SMEM>>>(xh, xl, Wh + 0 * WSZ, Wl + 0 * WSZ,
                                         bq, nullptr, 0);
    wmma_gemm<<<gGemm, blk, GEMM_SMEM>>>(xh, xl, Wh + 1 * WSZ, Wl + 1 * WSZ,
                                         bk, nullptr, 1);
    wmma_gemm<<<gGemm, blk, GEMM_SMEM>>>(xh, xl, Wh + 2 * WSZ, Wl + 2 * WSZ,
                                         bv, nullptr, 2);

    scores_wmma<<<dim3(S_ / 128, S_ / 128, BHn), blk, SC_SMEM>>>();
    softmax_heads<<<(unsigned)((size_t)B_ * S_ * S_ / 4 / 256), blk>>>();
    av_wmma<<<dim3(S_ / 128, BHn), blk, AV_SMEM>>>();

    conv_split<<<(M_ * E_ / 4 + 255) / 256, blk>>>(ctxp, ch, cl, M_ * E_ / 4);
    wmma_gemm<<<gGemm, blk, GEMM_SMEM>>>(ch, cl, Wh + 3 * WSZ, Wl + 3 * WSZ,
                                         bo, out, 3);
}

// round 16
// speedup vs baseline: 1.7646x; 1.4710x over previous
#include <cuda_runtime.h>
#include <cuda_bf16.h>
#include <cuda_fp16.h>
#include <mma.h>
#include <math.h>

// ---------------------------------------------------------------------------
// Problem dims (fixed)
// ---------------------------------------------------------------------------
#define S_  2048
#define B_  2
#define E_  1024
#define H_  16
#define D_  64
#define M_  (S_ * B_)
#define BHn (B_ * H_)
#define ST_ ((size_t)S_ * S_)

// ---------------------------------------------------------------------------
// Device scratch (static). Attention operands are fp16 (single product).
// ---------------------------------------------------------------------------
__device__ __align__(128) __half g_Qh[(size_t)BHn * S_ * D_];
__device__ __align__(128) __half g_Kh[(size_t)BHn * S_ * D_];
__device__ __align__(128) __half g_Vh[(size_t)BHn * S_ * D_];
__device__ float g_P[(size_t)BHn * ST_];                 // fp32 scores 512 MB
__device__ __align__(128) __half g_Ph[(size_t)BHn * ST_];
__device__ float g_ctx[(size_t)M_ * E_];

__device__ __align__(128) __nv_bfloat16 g_xh[(size_t)M_ * E_];
__device__ __align__(128) __nv_bfloat16 g_xl[(size_t)M_ * E_];
__device__ __align__(128) __nv_bfloat16 g_Wh[(size_t)4 * E_ * E_];
__device__ __align__(128) __nv_bfloat16 g_Wl[(size_t)4 * E_ * E_];
__device__ __align__(128) __nv_bfloat16 g_ch[(size_t)M_ * E_];
__device__ __align__(128) __nv_bfloat16 g_cl[(size_t)M_ * E_];

using namespace nvcuda;

// ---------------------------------------------------------------------------
// Split fp32 -> bf16 hi + bf16 lo (residual). Vectorized by 4.
// ---------------------------------------------------------------------------
__global__ void __launch_bounds__(256)
conv_split(const float* __restrict__ src, __nv_bfloat16* __restrict__ hi,
           __nv_bfloat16* __restrict__ lo, int n4)
{
    int idx = blockIdx.x * 256 + threadIdx.x;
    if (idx >= n4) return;
    float4 vin = reinterpret_cast<const float4*>(src)[idx];
    float vals[4];
    vals[0] = vin.x; vals[1] = vin.y; vals[2] = vin.z; vals[3] = vin.w;
    __nv_bfloat16 hiv[4];
    __nv_bfloat16 lov[4];
    #pragma unroll
    for (int j = 0; j < 4; ++j) {
        hiv[j] = __float2bfloat16_rn(vals[j]);
        lov[j] = __float2bfloat16_rn(vals[j] - __bfloat162float(hiv[j]));
    }
    __nv_bfloat162* hp = reinterpret_cast<__nv_bfloat162*>(hi);
    __nv_bfloat162* lp = reinterpret_cast<__nv_bfloat162*>(lo);
    hp[2 * idx + 0] = __nv_bfloat162(hiv[0], hiv[1]);
    hp[2 * idx + 1] = __nv_bfloat162(hiv[2], hiv[3]);
    lp[2 * idx + 0] = __nv_bfloat162(lov[0], lov[1]);
    lp[2 * idx + 1] = __nv_bfloat162(lov[2], lov[3]);
}

// ---------------------------------------------------------------------------
// WMMA projection GEMM. BM=BN=128, BK=32, 2-stage smem + reg prefetch,
// 3-product bf16 hi/lo split (input accuracy preserved), fp32 accum.
// mode 0/1/2: write FP16 into g_Qh/g_Kh/g_Vh [b][h][s][d].
// mode 3: fp32 outp[m][n].
// ---------------------------------------------------------------------------
#define SKP        40
#define TILE_E     (128 * SKP)
#define STAGE_E    (4 * TILE_E)
#define GEMM_SMEM  (2 * STAGE_E * 2)

__global__ void __launch_bounds__(256)
wmma_gemm(const __nv_bfloat16* __restrict__ Ahp, const __nv_bfloat16* __restrict__ Alp,
          const __nv_bfloat16* __restrict__ Whp, const __nv_bfloat16* __restrict__ Wlp,
          const float* __restrict__ bias, float* __restrict__ outp, int mode)
{
    extern __shared__ __align__(16) unsigned char smraw[];
    __nv_bfloat16* smb = reinterpret_cast<__nv_bfloat16*>(smraw);

    const int tid    = threadIdx.x;
    const int lane   = tid & 31;
    const int warpid = tid >> 5;
    const int warpM  = (warpid >> 2) << 6;
    const int warpN  = (warpid & 3) << 5;
    const int blockM = blockIdx.y << 7;
    const int blockN = blockIdx.x << 7;

    const __nv_bfloat16* gT[4];
    gT[0] = Ahp + (size_t)blockM * 1024;
    gT[1] = Alp + (size_t)blockM * 1024;
    gT[2] = Whp + (size_t)blockN * 1024;
    gT[3] = Wlp + (size_t)blockN * 1024;

    const int srow  = tid >> 1;
    const int shalf = tid & 1;

    wmma::fragment<wmma::accumulator, 16, 16, 16, float> accf[4][2];
    #pragma unroll
    for (int mi = 0; mi < 4; ++mi)
        #pragma unroll
        for (int nj = 0; nj < 2; ++nj)
            wmma::fill_fragment(accf[mi][nj], 0.0f);

    float4 pre[8];
    #pragma unroll
    for (int t = 0; t < 4; ++t)
        #pragma unroll
        for (int c = 0; c < 2; ++c)
            pre[t * 2 + c] = *reinterpret_cast<const float4*>(
                gT[t] + (size_t)srow * 1024 + (size_t)(shalf * 2 + c) * 8);
    #pragma unroll
    for (int t = 0; t < 4; ++t)
        #pragma unroll
        for (int c = 0; c < 2; ++c)
            *reinterpret_cast<float4*>(
                smb + t * TILE_E + srow * SKP + (shalf * 2 + c) * 8) = pre[t * 2 + c];

    for (int step = 0; step < 32; ++step) {
        if (step < 31) {
            size_t k0 = (size_t)(step + 1) * 32;
            #pragma unroll
            for (int t = 0; t < 4; ++t)
                #pragma unroll
                for (int c = 0; c < 2; ++c)
                    pre[t * 2 + c] = *reinterpret_cast<const float4*>(
                        gT[t] + (size_t)srow * 1024 + k0 + (size_t)(shalf * 2 + c) * 8);
        }
        __syncthreads();

        const __nv_bfloat16* stg = smb + (step & 1) * STAGE_E;
        #pragma unroll
        for (int kk = 0; kk < 2; ++kk) {
            wmma::fragment<wmma::matrix_a, 16, 16, 16, __nv_bfloat16, wmma::row_major> fAh[4];
            wmma::fragment<wmma::matrix_a, 16, 16, 16, __nv_bfloat16, wmma::row_major> fAl[4];
            wmma::fragment<wmma::matrix_b, 16, 16, 16, __nv_bfloat16, wmma::col_major> fBh[2];
            wmma::fragment<wmma::matrix_b, 16, 16, 16, __nv_bfloat16, wmma::col_major> fBl[2];
            #pragma unroll
            for (int mi = 0; mi < 4; ++mi) {
                wmma::load_matrix_sync(fAh[mi],
                    stg + 0 * TILE_E + (warpM + mi * 16) * SKP + kk * 16, SKP);
                wmma::load_matrix_sync(fAl[mi],
                    stg + 1 * TILE_E + (warpM + mi * 16) * SKP + kk * 16, SKP);
            }
            #pragma unroll
            for (int nj = 0; nj < 2; ++nj) {
                wmma::load_matrix_sync(fBh[nj],
                    stg + 2 * TILE_E + (warpN + nj * 16) * SKP + kk * 16, SKP);
                wmma::load_matrix_sync(fBl[nj],
                    stg + 3 * TILE_E + (warpN + nj * 16) * SKP + kk * 16, SKP);
            }
            #pragma unroll
            for (int mi = 0; mi < 4; ++mi) {
                #pragma unroll
                for (int nj = 0; nj < 2; ++nj) {
                    wmma::mma_sync(accf[mi][nj], fAh[mi], fBh[nj], accf[mi][nj]);
                    wmma::mma_sync(accf[mi][nj], fAh[mi], fBl[nj], accf[mi][nj]);
                    wmma::mma_sync(accf[mi][nj], fAl[mi], fBh[nj], accf[mi][nj]);
                }
            }
        }
        if (step < 31) {
            __nv_bfloat16* nstg = smb + ((step + 1) & 1) * STAGE_E;
            #pragma unroll
            for (int t = 0; t < 4; ++t)
                #pragma unroll
                for (int c = 0; c < 2; ++c)
                    *reinterpret_cast<float4*>(
                        nstg + t * TILE_E + srow * SKP + (shalf * 2 + c) * 8) = pre[t * 2 + c];
        }
    }

    __syncthreads();
    float* stgf = reinterpret_cast<float*>(smraw) + warpid * 576;

    __half* dsth = (mode == 0) ? g_Qh : (mode == 1) ? g_Kh : g_Vh;

    const int erow = lane >> 1;
    const int ecol = (lane & 1) * 16;

    #pragma unroll
    for (int mi = 0; mi < 4; ++mi) {
        wmma::store_matrix_sync(stgf + 0,  accf[mi][0], 36, wmma::mem_row_major);
        wmma::store_matrix_sync(stgf + 16, accf[mi][1], 36, wmma::mem_row_major);
        __syncwarp();

        int mRow = blockM + warpM + mi * 16 + erow;
        int col0 = blockN + warpN + ecol;

        float vv[16];
        #pragma unroll
        for (int c = 0; c < 4; ++c) {
            float4 t4 = *reinterpret_cast<const float4*>(stgf + erow * 36 + ecol + c * 4);
            float4 b4 = *reinterpret_cast<const float4*>(bias + col0 + c * 4);
            vv[c * 4 + 0] = t4.x + b4.x;
            vv[c * 4 + 1] = t4.y + b4.y;
            vv[c * 4 + 2] = t4.z + b4.z;
            vv[c * 4 + 3] = t4.w + b4.w;
        }

        if (mode <= 2) {
            int sE = mRow >> 1;
            int bE = mRow & 1;
            int hE = col0 >> 6;
            int dE = col0 & 63;
            unsigned int pwh[8];
            #pragma unroll
            for (int j = 0; j < 8; ++j) {
                __half h0 = __float2half_rn(vv[2 * j]);
                __half h1 = __float2half_rn(vv[2 * j + 1]);
                pwh[j] = (unsigned int)__half_as_ushort(h0)
                       | ((unsigned int)__half_as_ushort(h1) << 16);
            }
            size_t base = ((((size_t)bE * H_ + hE) * S_ + sE) << 6) + dE;
            uint4* ph = reinterpret_cast<uint4*>(dsth + base);
            ph[0] = make_uint4(pwh[0], pwh[1], pwh[2], pwh[3]);
            ph[1] = make_uint4(pwh[4], pwh[5], pwh[6], pwh[7]);
        } else {
            float* pd = outp + (size_t)mRow * 1024 + col0;
            #pragma unroll
            for (int c = 0; c < 4; ++c)
                *reinterpret_cast<float4*>(pd + c * 4)
                    = make_float4(vv[c*4+0], vv[c*4+1], vv[c*4+2], vv[c*4+3]);
        }
        __syncwarp();
    }
}

// ---------------------------------------------------------------------------
// Scores: P[bh][s][t] = (Q_bh . K_bh^T) / 8, SINGLE fp16 product, fp32 accum.
// BM=BN=128, K=64 one-shot.
// ---------------------------------------------------------------------------
#define AKP        72
#define SC_TILE_E  (128 * AKP)
#define SC_SMEM    (2 * SC_TILE_E * 2)

__global__ void __launch_bounds__(256)
scores_wmma()
{
    extern __shared__ __align__(16) unsigned char smraw[];
    __half* smb = reinterpret_cast<__half*>(smraw);
    __half* sQh = smb;
    __half* sKh = smb + SC_TILE_E;

    const int tid    = threadIdx.x;
    const int warpid = tid >> 5;
    const int warpM  = (warpid >> 2) << 6;
    const int warpN  = (warpid & 3) << 5;
    const int blockM = blockIdx.y << 7;
    const int blockN = blockIdx.x << 7;
    const int bh     = blockIdx.z;

    const size_t qoff = (size_t)bh * (S_ * D_);
    const int srow  = tid >> 1;
    const int shalf = tid & 1;

    #pragma unroll
    for (int c = 0; c < 4; ++c) {
        int scol = shalf * 4 + c;
        size_t gq = qoff + (size_t)(blockM + srow) * 64 + scol * 8;
        size_t gk = qoff + (size_t)(blockN + srow) * 64 + scol * 8;
        int so = srow * AKP + scol * 8;
        *reinterpret_cast<float4*>(sQh + so) = *reinterpret_cast<const float4*>(g_Qh + gq);
        *reinterpret_cast<float4*>(sKh + so) = *reinterpret_cast<const float4*>(g_Kh + gk);
    }
    __syncthreads();

    wmma::fragment<wmma::accumulator, 16, 16, 16, float> accf[4][2];
    #pragma unroll
    for (int mi = 0; mi < 4; ++mi)
        #pragma unroll
        for (int nj = 0; nj < 2; ++nj)
            wmma::fill_fragment(accf[mi][nj], 0.0f);

    #pragma unroll
    for (int kk = 0; kk < 4; ++kk) {
        wmma::fragment<wmma::matrix_a, 16, 16, 16, __half, wmma::row_major> fAh[4];
        wmma::fragment<wmma::matrix_b, 16, 16, 16, __half, wmma::col_major> fBh[2];
        #pragma unroll
        for (int mi = 0; mi < 4; ++mi)
            wmma::load_matrix_sync(fAh[mi], sQh + (warpM + mi * 16) * AKP + kk * 16, AKP);
        #pragma unroll
        for (int nj = 0; nj < 2; ++nj)
            wmma::load_matrix_sync(fBh[nj], sKh + (warpN + nj * 16) * AKP + kk * 16, AKP);
        #pragma unroll
        for (int mi = 0; mi < 4; ++mi)
            #pragma unroll
            for (int nj = 0; nj < 2; ++nj)
                wmma::mma_sync(accf[mi][nj], fAh[mi], fBh[nj], accf[mi][nj]);
    }

    float* pb = g_P + (size_t)bh * ST_;
    #pragma unroll
    for (int mi = 0; mi < 4; ++mi) {
        #pragma unroll
        for (int nj = 0; nj < 2; ++nj) {
            #pragma unroll
            for (int e = 0; e < accf[mi][nj].num_elements; ++e)
                accf[mi][nj].x[e] *= 0.125f;
            wmma::store_matrix_sync(
                pb + (size_t)(blockM + warpM + mi * 16) * S_ + blockN + warpN + nj * 16,
                accf[mi][nj], S_, wmma::mem_row_major);
        }
    }
}

// ---------------------------------------------------------------------------
// Softmax over HEADS, vectorized 4t/thread. Emits fp16.
// ---------------------------------------------------------------------------
__device__ __forceinline__ float exp_poly(float x)
{
    float t = x * 1.4426950408889634f;
    t = fmaxf(t, -80.0f);
    float fi = floorf(t);
    float f = t - fi;
    float p = 0.0001540353f;
    p = p * f + 0.0013333558f;
    p = p * f + 0.0096181291f;
    p = p * f + 0.0555041087f;
    p = p * f + 0.2402265069f;
    p = p * f + 0.6931471806f;
    p = p * f + 1.0f;
    int ei = (int)fi + 127;
    float sc = __uint_as_float(((unsigned int)ei) << 23);
    return p * sc;
}

__global__ void __launch_bounds__(256)
softmax_heads()
{
    size_t id = (size_t)blockIdx.x * 256 + threadIdx.x;
    int t4 = (int)(id & 511);
    int s  = (int)((id >> 9) & 2047);
    int b  = (int)(id >> 20);

    size_t base = (size_t)b * H_ * ST_ + (size_t)s * S_ + (size_t)t4 * 4;

    float4 v[H_];
    float4 mx = make_float4(-1e30f, -1e30f, -1e30f, -1e30f);
    #pragma unroll
    for (int h = 0; h < H_; ++h) {
        v[h] = *reinterpret_cast<const float4*>(g_P + base + (size_t)h * ST_);
        mx.x = fmaxf(mx.x, v[h].x);
        mx.y = fmaxf(mx.y, v[h].y);
        mx.z = fmaxf(mx.z, v[h].z);
        mx.w = fmaxf(mx.w, v[h].w);
    }
    float4 sum = make_float4(0.f, 0.f, 0.f, 0.f);
    #pragma unroll
    for (int h = 0; h < H_; ++h) {
        v[h].x = exp_poly(v[h].x - mx.x);
        v[h].y = exp_poly(v[h].y - mx.y);
        v[h].z = exp_poly(v[h].z - mx.z);
        v[h].w = exp_poly(v[h].w - mx.w);
        sum.x += v[h].x;
        sum.y += v[h].y;
        sum.z += v[h].z;
        sum.w += v[h].w;
    }
    float4 inv;
    inv.x = __fdividef(1.0f, sum.x);
    inv.y = __fdividef(1.0f, sum.y);
    inv.z = __fdividef(1.0f, sum.z);
    inv.w = __fdividef(1.0f, sum.w);

    #pragma unroll
    for (int h = 0; h < H_; ++h) {
        float p0 = v[h].x * inv.x;
        float p1 = v[h].y * inv.y;
        float p2 = v[h].z * inv.z;
        float p3 = v[h].w * inv.w;
        __half h0 = __float2half_rn(p0);
        __half h1 = __float2half_rn(p1);
        __half h2 = __float2half_rn(p2);
        __half h3 = __float2half_rn(p3);
        uint2 wh;
        wh.x = (unsigned int)__half_as_ushort(h0)
             | ((unsigned int)__half_as_ushort(h1) << 16);
        wh.y = (unsigned int)__half_as_ushort(h2)
             | ((unsigned int)__half_as_ushort(h3) << 16);
        *reinterpret_cast<uint2*>(g_Ph + base + (size_t)h * ST_) = wh;
    }
}

// ---------------------------------------------------------------------------
// AV: ctx = P @ V, SINGLE fp16 product, fp32 accum. 2-stage reg prefetch.
// ---------------------------------------------------------------------------
#define AV_PT_E   (128 * AKP)
#define AV_VT_E   (64 * AKP)
#define AV_STAGE  (AV_PT_E + AV_VT_E)
#define AV_SMEM   (2 * AV_STAGE * 2)

__global__ void __launch_bounds__(256)
av_wmma()
{
    extern __shared__ __align__(16) unsigned char smraw[];
    __half* smb = reinterpret_cast<__half*>(smraw);

    const int tid    = threadIdx.x;
    const int warpid = tid >> 5;
    const int warpM  = (warpid >> 1) << 5;
    const int warpN  = (warpid & 1) << 5;
    const int blockM = blockIdx.x << 7;
    const int bh     = blockIdx.y;
    const int bE     = bh >> 4;
    const int hE     = bh & 15;

    const __half* gPh = g_Ph + (size_t)bh * ST_;
    const __half* gVh = g_Vh + (size_t)bh * (S_ * D_);

    const int prow  = tid >> 1;
    const int phalf = tid & 1;
    const int vrow  = tid >> 2;
    const int vcol  = tid & 3;

    wmma::fragment<wmma::accumulator, 16, 16, 16, float> accf[2][2];
    #pragma unroll
    for (int mi = 0; mi < 2; ++mi)
        #pragma unroll
        for (int nj = 0; nj < 2; ++nj)
            wmma::fill_fragment(accf[mi][nj], 0.0f);

    float4 pre[6];
    #pragma unroll
    for (int c = 0; c < 4; ++c) {
        int scol = phalf * 4 + c;
        pre[c] = *reinterpret_cast<const float4*>(
            gPh + (size_t)(blockM + prow) * S_ + scol * 8);
    }
    #pragma unroll
    for (int c = 0; c < 2; ++c) {
        int scol = vcol * 2 + c;
        pre[4 + c] = *reinterpret_cast<const float4*>(
            gVh + (size_t)vrow * 64 + scol * 8);
    }

    {
        __half* st = smb;
        #pragma unroll
        for (int c = 0; c < 4; ++c) {
            int scol = phalf * 4 + c;
            *reinterpret_cast<float4*>(st + prow * AKP + scol * 8) = pre[c];
        }
        #pragma unroll
        for (int c = 0; c < 2; ++c) {
            int scol = vcol * 2 + c;
            *reinterpret_cast<float4*>(st + AV_PT_E + vrow * AKP + scol * 8) = pre[4 + c];
        }
    }

    for (int step = 0; step < 32; ++step) {
        if (step < 31) {
            size_t k0 = (size_t)(step + 1) * 64;
            #pragma unroll
            for (int c = 0; c < 4; ++c) {
                int scol = phalf * 4 + c;
                pre[c] = *reinterpret_cast<const float4*>(
                    gPh + (size_t)(blockM + prow) * S_ + k0 + scol * 8);
            }
            #pragma unroll
            for (int c = 0; c < 2; ++c) {
                int scol = vcol * 2 + c;
                pre[4 + c] = *reinterpret_cast<const float4*>(
                    gVh + (size_t)(k0 + vrow) * 64 + scol * 8);
            }
        }
        __syncthreads();

        const __half* st = smb + (step & 1) * AV_STAGE;
        const __half* sPh = st;
        const __half* sVh = st + AV_PT_E;

        #pragma unroll
        for (int kk = 0; kk < 4; ++kk) {
            wmma::fragment<wmma::matrix_a, 16, 16, 16, __half, wmma::row_major> fAh[2];
            wmma::fragment<wmma::matrix_b, 16, 16, 16, __half, wmma::row_major> fBh[2];
            #pragma unroll
            for (int mi = 0; mi < 2; ++mi)
                wmma::load_matrix_sync(fAh[mi], sPh + (warpM + mi * 16) * AKP + kk * 16, AKP);
            #pragma unroll
            for (int nj = 0; nj < 2; ++nj)
                wmma::load_matrix_sync(fBh[nj], sVh + (kk * 16) * AKP + warpN + nj * 16, AKP);
            #pragma unroll
            for (int mi = 0; mi < 2; ++mi)
                #pragma unroll
                for (int nj = 0; nj < 2; ++nj)
                    wmma::mma_sync(accf[mi][nj], fAh[mi], fBh[nj], accf[mi][nj]);
        }
        if (step < 31) {
            __half* nst = smb + ((step + 1) & 1) * AV_STAGE;
            #pragma unroll
            for (int c = 0; c < 4; ++c) {
                int scol = phalf * 4 + c;
                *reinterpret_cast<float4*>(nst + prow * AKP + scol * 8) = pre[c];
            }
            #pragma unroll
            for (int c = 0; c < 2; ++c) {
                int scol = vcol * 2 + c;
                *reinterpret_cast<float4*>(nst + AV_PT_E + vrow * AKP + scol * 8) = pre[4 + c];
            }
        }
    }

    #pragma unroll
    for (int mi = 0; mi < 2; ++mi) {
        #pragma unroll
        for (int nj = 0; nj < 2; ++nj) {
            float* pd = g_ctx + (size_t)(blockM + warpM + mi * 16) * (B_ * E_)
                      + (size_t)bE * E_ + hE * 64 + warpN + nj * 16;
            wmma::store_matrix_sync(pd, accf[mi][nj], B_ * E_, wmma::mem_row_major);
        }
    }
}

// ---------------------------------------------------------------------------
// Launch. Inputs (metadata order): x, Wq, bq, Wk, bk, Wv, bv, Wo, bo
// ---------------------------------------------------------------------------
extern "C" void kernel_launch(void* const* d_in, const int* in_sizes, int n_in,
                              void* d_out, int out_size)
{
    const float* x  = (const float*)d_in[0];
    const float* Wq = (const float*)d_in[1];
    const float* bq = (const float*)d_in[2];
    const float* Wk = (const float*)d_in[3];
    const float* bk = (const float*)d_in[4];
    const float* Wv = (const float*)d_in[5];
    const float* bv = (const float*)d_in[6];
    const float* Wo = (const float*)d_in[7];
    const float* bo = (const float*)d_in[8];
    float* out = (float*)d_out;

    cudaFuncSetAttribute(wmma_gemm,
                         cudaFuncAttributeMaxDynamicSharedMemorySize, GEMM_SMEM);
    cudaFuncSetAttribute(scores_wmma,
                         cudaFuncAttributeMaxDynamicSharedMemorySize, SC_SMEM);
    cudaFuncSetAttribute(av_wmma,
                         cudaFuncAttributeMaxDynamicSharedMemorySize, AV_SMEM);

    __nv_bfloat16* xh;
    __nv_bfloat16* xl;
    __nv_bfloat16* Wh;
    __nv_bfloat16* Wl;
    __nv_bfloat16* ch;
    __nv_bfloat16* cl;
    float* ctxp;
    cudaGetSymbolAddress((void**)&xh, g_xh);
    cudaGetSymbolAddress((void**)&xl, g_xl);
    cudaGetSymbolAddress((void**)&Wh, g_Wh);
    cudaGetSymbolAddress((void**)&Wl, g_Wl);
    cudaGetSymbolAddress((void**)&ch, g_ch);
    cudaGetSymbolAddress((void**)&cl, g_cl);
    cudaGetSymbolAddress((void**)&ctxp, g_ctx);

    const size_t WSZ = (size_t)E_ * E_;
    dim3 blk(256);

    conv_split<<<(M_ * E_ / 4 + 255) / 256, blk>>>(x,  xh, xl, M_ * E_ / 4);
    conv_split<<<(WSZ / 4 + 255) / 256, blk>>>(Wq, Wh + 0 * WSZ, Wl + 0 * WSZ, WSZ / 4);
    conv_split<<<(WSZ / 4 + 255) / 256, blk>>>(Wk, Wh + 1 * WSZ, Wl + 1 * WSZ, WSZ / 4);
    conv_split<<<(WSZ / 4 + 255) / 256, blk>>>(Wv, Wh + 2 * WSZ, Wl + 2 * WSZ, WSZ / 4);
    conv_split<<<(WSZ / 4 + 255) / 256, blk>>>(Wo, Wh + 3 * WSZ, Wl + 3 * WSZ, WSZ / 4);

    dim3 gGemm(E_ / 128, M_ / 128);
    wmma_gemm<<<gGemm, blk, GEMM_SMEM>>>(xh, xl, Wh + 0 * WSZ, Wl + 0 * WSZ,
                                         bq, nullptr, 0);
    wmma_gemm<<<gGemm, blk, GEMM_SMEM>>>(xh, xl, Wh + 1 * WSZ, Wl + 1 * WSZ,
                                         bk, nullptr, 1);
    wmma_gemm<<<gGemm, blk, GEMM_SMEM>>>(xh, xl, Wh + 2 * WSZ, Wl + 2 * WSZ,
                                         bv, nullptr, 2);

    scores_wmma<<<dim3(S_ / 128, S_ / 128, BHn), blk, SC_SMEM>>>();
    softmax_heads<<<(unsigned)((size_t)B_ * S_ * S_ / 4 / 256), blk>>>();
    av_wmma<<<dim3(S_ / 128, BHn), blk, AV_SMEM>>>();

    conv_split<<<(M_ * E_ / 4 + 255) / 256, blk>>>(ctxp, ch, cl, M_ * E_ / 4);
    wmma_gemm<<<gGemm, blk, GEMM_SMEM>>>(ch, cl, Wh + 3 * WSZ, Wl + 3 * WSZ,
                                         bo, out, 3);
}